// round 2
// baseline (speedup 1.0000x reference)
#include <cuda_runtime.h>
#include <cstdint>
#include <cstddef>

typedef unsigned long long ull;

#define SLICES 96
#define NN 250
#define NP 256
#define SEG 18000000ULL   // 96*250*750 elements per output segment

// Scratch (device globals; no allocation)
__device__ float g_V[SLICES * NN * 64];       // nodevec
__device__ float g_S[SLICES * NN * NP];       // relu(V V^T), padded cols to 256
__device__ float g_part[SLICES * 4 * NP];     // per-jtile row partial sums
__device__ float g_a[SLICES * NP];
__device__ float g_c[SLICES * NP];
__device__ float g_gv[SLICES * NP];

// ---------- f32x2 helpers ----------
__device__ __forceinline__ ull pack2(float x) {
    ull r; asm("mov.b64 %0, {%1, %1};" : "=l"(r) : "f"(x)); return r;
}
__device__ __forceinline__ void fma2(ull& d, ull a, ull b) {
    asm("fma.rn.f32x2 %0, %1, %2, %0;" : "+l"(d) : "l"(a), "l"(b));
}
__device__ __forceinline__ float2 unpack2(ull v) {
    float2 f; asm("mov.b64 {%0, %1}, %2;" : "=f"(f.x), "=f"(f.y) : "l"(v)); return f;
}

// ---------- K1: nodevec = tanh(concat(X) @ W + b) ----------
__global__ void __launch_bounds__(256) k_embed(
    const float* __restrict__ hist, const float* __restrict__ prior,
    const float* __restrict__ obs, const float* __restrict__ W,
    const float* __restrict__ bias)
{
    __shared__ float Xs[16][224];
    int row0 = blockIdx.x * 16;
    int tid = threadIdx.x;
    for (int idx = tid; idx < 16 * 224; idx += 256) {
        int r = idx / 224, k = idx - r * 224;
        int g = row0 + r;
        float v;
        if (k < 128)      v = hist [g * 128 + k];
        else if (k < 192) v = prior[g * 64  + (k - 128)];
        else              v = obs  [g * 32  + (k - 192)];
        Xs[r][k] = v;
    }
    __syncthreads();
    int c = tid & 63, r0 = tid >> 6;
    float a0 = 0.f, a1 = 0.f, a2 = 0.f, a3 = 0.f;
#pragma unroll 4
    for (int k = 0; k < 224; k++) {
        float w = W[k * 64 + c];
        a0 = fmaf(Xs[r0][k],      w, a0);
        a1 = fmaf(Xs[r0 + 4][k],  w, a1);
        a2 = fmaf(Xs[r0 + 8][k],  w, a2);
        a3 = fmaf(Xs[r0 + 12][k], w, a3);
    }
    float bb = bias[c];
    g_V[(row0 + r0)      * 64 + c] = tanhf(a0 + bb);
    g_V[(row0 + r0 + 4)  * 64 + c] = tanhf(a1 + bb);
    g_V[(row0 + r0 + 8)  * 64 + c] = tanhf(a2 + bb);
    g_V[(row0 + r0 + 12) * 64 + c] = tanhf(a3 + bb);
}

// ---------- K2: S = relu(V V^T) + per-jtile row sums ----------
__global__ void __launch_bounds__(256) k_sim()
{
    __shared__ float As[64][65];
    __shared__ float Bs[64][65];
    int slice = blockIdx.z;
    int i0 = blockIdx.y * 64, j0 = blockIdx.x * 64;
    int tx = threadIdx.x, ty = threadIdx.y;
    int tid = ty * 16 + tx;
    const float* Vb = g_V + (size_t)slice * NN * 64;

    for (int t = tid; t < 4096; t += 256) {
        int a = t >> 6, k = t & 63;
        int i = i0 + a;
        As[k][a] = (i < NN) ? Vb[i * 64 + k] : 0.f;
        int j = j0 + a;
        Bs[k][a] = (j < NN) ? Vb[j * 64 + k] : 0.f;
    }
    __syncthreads();

    float acc[4][4];
#pragma unroll
    for (int r = 0; r < 4; r++)
#pragma unroll
        for (int q = 0; q < 4; q++) acc[r][q] = 0.f;

#pragma unroll 8
    for (int k = 0; k < 64; k++) {
        float av[4], bv[4];
#pragma unroll
        for (int r = 0; r < 4; r++) av[r] = As[k][ty * 4 + r];
#pragma unroll
        for (int q = 0; q < 4; q++) bv[q] = Bs[k][tx * 4 + q];
#pragma unroll
        for (int r = 0; r < 4; r++)
#pragma unroll
            for (int q = 0; q < 4; q++) acc[r][q] = fmaf(av[r], bv[q], acc[r][q]);
    }

    float* Sb = g_S + (size_t)slice * NN * NP;
#pragma unroll
    for (int r = 0; r < 4; r++) {
        int i = i0 + ty * 4 + r;
        float rs = 0.f;
#pragma unroll
        for (int q = 0; q < 4; q++) {
            int j = j0 + tx * 4 + q;
            float s = fmaxf(acc[r][q], 0.f);
            if (j < NN) {
                rs += s;
                if (i < NN) Sb[(size_t)i * NP + j] = s;
            }
        }
        rs += __shfl_xor_sync(0xffffffffu, rs, 8);
        rs += __shfl_xor_sync(0xffffffffu, rs, 4);
        rs += __shfl_xor_sync(0xffffffffu, rs, 2);
        rs += __shfl_xor_sync(0xffffffffu, rs, 1);
        if (tx == 0 && i < NN)
            g_part[(slice * 4 + blockIdx.x) * NP + i] = rs;
    }
}

// ---------- K3: scalars a = d, c = d/r, g = d^2/r ----------
__global__ void __launch_bounds__(256) k_scal()
{
    int slice = blockIdx.x;
    int i = threadIdx.x;
    __shared__ float ds[NP];
    float d = 0.f;
    if (i < NN) {
        const float* p = g_part + slice * 4 * NP;
        float s = p[i] + p[NP + i] + p[2 * NP + i] + p[3 * NP + i];
        d = rsqrtf(s + 1e-9f);
    }
    ds[i] = d;
    __syncthreads();
    float a = 0.f, c = 0.f, gv = 0.f;
    if (i < NN) {
        const float* Srow = g_S + ((size_t)slice * NN + i) * NP;
        float t = 0.f;
#pragma unroll 4
        for (int j = 0; j < 248; j += 4) {
            float4 v = *reinterpret_cast<const float4*>(Srow + j);
            t = fmaf(v.x, ds[j],     t);
            t = fmaf(v.y, ds[j + 1], t);
            t = fmaf(v.z, ds[j + 2], t);
            t = fmaf(v.w, ds[j + 3], t);
        }
        t = fmaf(Srow[248], ds[248], t);
        t = fmaf(Srow[249], ds[249], t);
        float r = d * t + 1e-9f;
        a = d; c = d / r; gv = d * c;
    }
    g_a[slice * NP + i] = a;
    g_c[slice * NP + i] = c;
    g_gv[slice * NP + i] = gv;
}

// ---------- K4: order-1 outputs (P*mask tiled x3) -> seg0 and seg2 ----------
__global__ void __launch_bounds__(256) k_out1(float* __restrict__ out)
{
    int slice = blockIdx.y;
    int n = blockIdx.x * 2 + (threadIdx.x >> 7);
    int m = (threadIdx.x & 127) * 2;
    if (m >= NN) return;
    float an = g_a[slice * NP + n];
    float2 s  = *reinterpret_cast<const float2*>(g_S + ((size_t)slice * NN + n) * NP + m);
    float2 cc = *reinterpret_cast<const float2*>(g_c + slice * NP + m);
    float2 v;
    v.x = (m     == n) ? 0.f : an * s.x * cc.x;
    v.y = (m + 1 == n) ? 0.f : an * s.y * cc.y;
    size_t base = ((size_t)(slice * NN + n)) * 750;
    float* o0 = out + base;
    float* o2 = out + 2 * SEG + base;
#pragma unroll
    for (int kt = 0; kt < 3; kt++) {
        *reinterpret_cast<float2*>(o0 + kt * 250 + m) = v;
        *reinterpret_cast<float2*>(o2 + kt * 250 + m) = v;
    }
}

// ---------- K5: M = S diag(g) S (f32x2 GEMM) + order-2 outputs -> seg1, seg3 ----------
__global__ void __launch_bounds__(256) k_gemm2(float* __restrict__ out)
{
    __shared__ float As[64][65];
    __shared__ float Bs[64][64];
    int slice = blockIdx.z;
    int i0 = blockIdx.y * 64, j0 = blockIdx.x * 64;
    int tx = threadIdx.x, ty = threadIdx.y;
    int tid = ty * 16 + tx;
    const float* Sb = g_S + (size_t)slice * NN * NP;
    const float* gg = g_gv + slice * NP;

    ull acc[4][2];
#pragma unroll
    for (int r = 0; r < 4; r++) { acc[r][0] = 0ULL; acc[r][1] = 0ULL; }

    for (int k0 = 0; k0 < NN; k0 += 64) {
        __syncthreads();
        for (int t = tid; t < 4096; t += 256) {
            int x = t >> 6, y = t & 63;
            int i = i0 + x, ka = k0 + y;
            As[y][x] = (i < NN && ka < NN) ? Sb[(size_t)i * NP + ka] : 0.f;
            int kb = k0 + x, j = j0 + y;
            Bs[x][y] = (kb < NN && j < NN) ? gg[kb] * Sb[(size_t)kb * NP + j] : 0.f;
        }
        __syncthreads();
#pragma unroll 8
        for (int k = 0; k < 64; k++) {
            const ull* bp = reinterpret_cast<const ull*>(&Bs[k][0]);
            ull b0 = bp[tx];       // cols j0 + 2tx, 2tx+1
            ull b1 = bp[16 + tx];  // cols j0 + 32 + 2tx, +1
            ull a0 = pack2(As[k][ty * 4 + 0]);
            ull a1 = pack2(As[k][ty * 4 + 1]);
            ull a2 = pack2(As[k][ty * 4 + 2]);
            ull a3 = pack2(As[k][ty * 4 + 3]);
            fma2(acc[0][0], a0, b0); fma2(acc[0][1], a0, b1);
            fma2(acc[1][0], a1, b0); fma2(acc[1][1], a1, b1);
            fma2(acc[2][0], a2, b0); fma2(acc[2][1], a2, b1);
            fma2(acc[3][0], a3, b0); fma2(acc[3][1], a3, b1);
        }
    }

    int jA = j0 + tx * 2, jB = j0 + 32 + tx * 2;
    float2 cA = *reinterpret_cast<const float2*>(g_c + slice * NP + jA);
    float2 cB = *reinterpret_cast<const float2*>(g_c + slice * NP + jB);

#pragma unroll
    for (int r = 0; r < 4; r++) {
        int i = i0 + ty * 4 + r;
        if (i >= NN) continue;
        float ai = g_a[slice * NP + i];
        float2 m0 = unpack2(acc[r][0]);
        float2 m1 = unpack2(acc[r][1]);
        float2 vA, vB;
        vA.x = (i == jA)     ? 0.f : ai * m0.x * cA.x;
        vA.y = (i == jA + 1) ? 0.f : ai * m0.y * cA.y;
        vB.x = (i == jB)     ? 0.f : ai * m1.x * cB.x;
        vB.y = (i == jB + 1) ? 0.f : ai * m1.y * cB.y;
        size_t base = ((size_t)(slice * NN + i)) * 750;
        float* o1 = out + SEG + base;
        float* o3 = out + 3 * SEG + base;
#pragma unroll
        for (int kt = 0; kt < 3; kt++) {
            if (jA < NN) {
                *reinterpret_cast<float2*>(o1 + kt * 250 + jA) = vA;
                *reinterpret_cast<float2*>(o3 + kt * 250 + jA) = vA;
            }
            if (jB < NN) {
                *reinterpret_cast<float2*>(o1 + kt * 250 + jB) = vB;
                *reinterpret_cast<float2*>(o3 + kt * 250 + jB) = vB;
            }
        }
    }
}

extern "C" void kernel_launch(void* const* d_in, const int* in_sizes, int n_in,
                              void* d_out, int out_size)
{
    const float* hist  = (const float*)d_in[0];
    const float* prior = (const float*)d_in[1];
    const float* obs   = (const float*)d_in[2];
    const float* W     = (const float*)d_in[3];
    const float* bias  = (const float*)d_in[4];
    float* out = (float*)d_out;

    k_embed<<<1500, 256>>>(hist, prior, obs, W, bias);
    k_sim  <<<dim3(4, 4, SLICES), dim3(16, 16)>>>();
    k_scal <<<SLICES, 256>>>();
    k_out1 <<<dim3(125, SLICES), 256>>>(out);
    k_gemm2<<<dim3(4, 4, SLICES), dim3(16, 16)>>>(out);
}